// round 7
// baseline (speedup 1.0000x reference)
#include <cuda_runtime.h>
#include <cuda_bf16.h>
#include <cstdint>

#define B_ROWS 16384
#define F_DIM  1024
#define C_COLS 1000
#define C_PAD  1024

// Scratch: normalized, per-row int8-quantized operands + dequant scales
__device__ uint8_t g_Fb[(size_t)B_ROWS * F_DIM];   // features, s8 (q = rint(127 v / rowmax))
__device__ uint8_t g_Pb[(size_t)C_PAD * F_DIM];    // prototypes (padded), s8
__device__ float g_Fs[B_ROWS];                     // feature dequant scale per row
__device__ float g_Ps[C_PAD];                      // prototype dequant scale per row(col)
__device__ float g_rowsum[B_ROWS];

// ---------------------------------------------------------------------------
// Helpers (base-ISA only: cp.async, ldmatrix, s8 mma.sync — ptxas target is
// plain sm_103, no 'a' features)
// ---------------------------------------------------------------------------
__device__ __forceinline__ uint32_t smem_u32(const void* p) {
    uint32_t a;
    asm("{ .reg .u64 t; cvta.to.shared.u64 t, %1; cvt.u32.u64 %0, t; }" : "=r"(a) : "l"(p));
    return a;
}
__device__ __forceinline__ void cp_async16(uint32_t dst, const void* src) {
    asm volatile("cp.async.cg.shared.global [%0], [%1], 16;" :: "r"(dst), "l"(src));
}
__device__ __forceinline__ void cp_commit() { asm volatile("cp.async.commit_group;" ::: "memory"); }

__device__ __forceinline__ void ldsm_x4(uint32_t& r0, uint32_t& r1, uint32_t& r2, uint32_t& r3,
                                        uint32_t addr) {
    asm volatile("ldmatrix.sync.aligned.m8n8.x4.shared.b16 {%0,%1,%2,%3}, [%4];"
                 : "=r"(r0), "=r"(r1), "=r"(r2), "=r"(r3) : "r"(addr));
}
__device__ __forceinline__ void mma_s8(int* c, uint32_t a0, uint32_t a1, uint32_t a2,
                                       uint32_t a3, uint32_t b0, uint32_t b1) {
    asm volatile(
        "mma.sync.aligned.m16n8k32.row.col.s32.s8.s8.s32 "
        "{%0,%1,%2,%3}, {%4,%5,%6,%7}, {%8,%9}, {%0,%1,%2,%3};"
        : "+r"(c[0]), "+r"(c[1]), "+r"(c[2]), "+r"(c[3])
        : "r"(a0), "r"(a1), "r"(a2), "r"(a3), "r"(b0), "r"(b1));
}

// ---------------------------------------------------------------------------
// Kernels 1/2: L2-normalize rows, per-row symmetric int8 quantization.
// q_i = rint(127 * v_i / max|v_row|); dequant scale = max|v_row| / (127*norm)
// ---------------------------------------------------------------------------
__global__ void __launch_bounds__(256) norm_features_kernel(const float* __restrict__ in) {
    int row = blockIdx.x, tid = threadIdx.x;
    const float4* rin = (const float4*)(in + (size_t)row * F_DIM);
    float4 v = rin[tid];
    float ss = v.x * v.x + v.y * v.y + v.z * v.z + v.w * v.w;
    float mv = fmaxf(fmaxf(fabsf(v.x), fabsf(v.y)), fmaxf(fabsf(v.z), fabsf(v.w)));
#pragma unroll
    for (int o = 16; o; o >>= 1) {
        ss += __shfl_xor_sync(0xffffffffu, ss, o);
        mv = fmaxf(mv, __shfl_xor_sync(0xffffffffu, mv, o));
    }
    __shared__ float red[8], redm[8];
    if ((tid & 31) == 0) { red[tid >> 5] = ss; redm[tid >> 5] = mv; }
    __syncthreads();
    if (tid < 8) {
        float t = red[tid], tm = redm[tid];
#pragma unroll
        for (int o = 4; o; o >>= 1) {
            t += __shfl_xor_sync(0x000000ffu, t, o);
            tm = fmaxf(tm, __shfl_xor_sync(0x000000ffu, tm, o));
        }
        if (tid == 0) { red[0] = t; redm[0] = tm; }
    }
    __syncthreads();
    float sc = 1.0f / fmaxf(sqrtf(red[0]), 1e-12f);
    float m  = fmaxf(redm[0], 1e-20f);
    float qs = 127.0f / m;
    int q0 = __float2int_rn(v.x * qs), q1 = __float2int_rn(v.y * qs);
    int q2 = __float2int_rn(v.z * qs), q3 = __float2int_rn(v.w * qs);
    uint32_t w = (q0 & 0xFF) | ((q1 & 0xFF) << 8) | ((q2 & 0xFF) << 16) | ((q3 & 0xFF) << 24);
    ((uint32_t*)g_Fb)[(size_t)row * 256 + tid] = w;
    if (tid == 0) {
        g_rowsum[row] = 0.0f;
        g_Fs[row] = m * sc * (1.0f / 127.0f);
    }
}

__global__ void __launch_bounds__(256) norm_protos_kernel(const float* __restrict__ in) {
    int row = blockIdx.x, tid = threadIdx.x;
    uint32_t* dst = (uint32_t*)g_Pb + (size_t)row * 256;
    if (row >= C_COLS) {
        dst[tid] = 0u;
        if (tid == 0) g_Ps[row] = 0.0f;
        return;
    }
    const float4* rin = (const float4*)(in + (size_t)row * F_DIM);
    float4 v = rin[tid];
    float ss = v.x * v.x + v.y * v.y + v.z * v.z + v.w * v.w;
    float mv = fmaxf(fmaxf(fabsf(v.x), fabsf(v.y)), fmaxf(fabsf(v.z), fabsf(v.w)));
#pragma unroll
    for (int o = 16; o; o >>= 1) {
        ss += __shfl_xor_sync(0xffffffffu, ss, o);
        mv = fmaxf(mv, __shfl_xor_sync(0xffffffffu, mv, o));
    }
    __shared__ float red[8], redm[8];
    if ((tid & 31) == 0) { red[tid >> 5] = ss; redm[tid >> 5] = mv; }
    __syncthreads();
    if (tid < 8) {
        float t = red[tid], tm = redm[tid];
#pragma unroll
        for (int o = 4; o; o >>= 1) {
            t += __shfl_xor_sync(0x000000ffu, t, o);
            tm = fmaxf(tm, __shfl_xor_sync(0x000000ffu, tm, o));
        }
        if (tid == 0) { red[0] = t; redm[0] = tm; }
    }
    __syncthreads();
    float sc = 1.0f / fmaxf(sqrtf(red[0]), 1e-12f);
    float m  = fmaxf(redm[0], 1e-20f);
    float qs = 127.0f / m;
    int q0 = __float2int_rn(v.x * qs), q1 = __float2int_rn(v.y * qs);
    int q2 = __float2int_rn(v.z * qs), q3 = __float2int_rn(v.w * qs);
    dst[tid] = (q0 & 0xFF) | ((q1 & 0xFF) << 8) | ((q2 & 0xFF) << 16) | ((q3 & 0xFF) << 24);
    if (tid == 0) g_Ps[row] = m * sc * (1.0f / 127.0f);
}

// ---------------------------------------------------------------------------
// Kernel 3: s8 IMMA GEMM, CTA 128x128, BK=128 s8, 2-stage cp.async pipeline
// 72KB smem -> 2 CTAs/SM (16 warps/SM).
// 8 warps: wm = wid>>2 (0..1, 64 rows each), wn = wid&3 (0..3, 32 cols each)
// Epilogue: sim = acc * fS[row]*pS[col]; iso = |ds|*sqrt(max(1-sim,0))
// ---------------------------------------------------------------------------
#define STAGES 2
#define BK 128                        // s8 elements per chunk (128 bytes/row)
#define KCHUNKS (F_DIM / BK)          // 8
#define PAD_BYTES 144                 // 128B data + 16B pad per row
#define A_ST_BYTES (128 * PAD_BYTES)  // 18432
#define STAGE_BYTES (2 * A_ST_BYTES)  // 36864 (A then B)
#define GEMM_SMEM (STAGES * STAGE_BYTES)   // 73728

__device__ __forceinline__ void load_tile(uint32_t base, int kc, int m0, int n0, int tid) {
    const char* fb = (const char*)g_Fb;
    const char* pb = (const char*)g_Pb;
    uint32_t st = base + (uint32_t)(kc & (STAGES - 1)) * STAGE_BYTES;
#pragma unroll
    for (int it = 0; it < 4; it++) {
        int s = tid + it * 256;            // 0..1023
        int r = s >> 3, q = s & 7;
        cp_async16(st + (uint32_t)(r * PAD_BYTES + q * 16),
                   fb + (size_t)(m0 + r) * 1024 + (size_t)kc * 128 + q * 16);
    }
    uint32_t stB = st + A_ST_BYTES;
#pragma unroll
    for (int it = 0; it < 4; it++) {
        int s = tid + it * 256;
        int r = s >> 3, q = s & 7;
        cp_async16(stB + (uint32_t)(r * PAD_BYTES + q * 16),
                   pb + (size_t)(n0 + r) * 1024 + (size_t)kc * 128 + q * 16);
    }
    cp_commit();
}

__global__ void __launch_bounds__(256, 2) gemm_kernel(const float* __restrict__ ds,
                                                      float* __restrict__ out) {
    extern __shared__ char smem_raw[];
    uint32_t base = smem_u32(smem_raw);

    int tid = threadIdx.x;
    int wid = tid >> 5, l = tid & 31;
    int wm = wid >> 2, wn = wid & 3;
    int m0 = blockIdx.y * 128, n0 = blockIdx.x * 128;

    int c[4][4][4];
#pragma unroll
    for (int i = 0; i < 4; i++)
#pragma unroll
        for (int j = 0; j < 4; j++)
#pragma unroll
            for (int k = 0; k < 4; k++) c[i][j][k] = 0;

    // prologue: prefetch chunk 0
    load_tile(base, 0, m0, n0, tid);

    for (int kc = 0; kc < KCHUNKS; kc++) {
        asm volatile("cp.async.wait_group 0;" ::: "memory");
        __syncthreads();

        int j = kc + 1;
        if (j < KCHUNKS) load_tile(base, j, m0, n0, tid);

        uint32_t st = base + (uint32_t)(kc & (STAGES - 1)) * STAGE_BYTES;
        uint32_t aBase = st + (uint32_t)(wm * 64) * PAD_BYTES;
        uint32_t bBase = st + A_ST_BYTES + (uint32_t)(wn * 32) * PAD_BYTES;

        int g = l >> 3;          // 0..3
        int r8 = l & 7;
        // each ks covers 32 s8 of K = 32 bytes
#pragma unroll
        for (int ks = 0; ks < 4; ks++) {
            uint32_t a[4][4];
#pragma unroll
            for (int mt = 0; mt < 4; mt++) {
                // matrices: g0 rows 0-7 kB0 | g1 rows 8-15 kB0 | g2 rows 0-7 kB16 | g3 rows 8-15 kB16
                uint32_t addr = aBase + (uint32_t)((mt * 16 + (g & 1) * 8 + r8) * PAD_BYTES
                                                  + ks * 32 + (g >> 1) * 16);
                ldsm_x4(a[mt][0], a[mt][1], a[mt][2], a[mt][3], addr);
            }
            uint32_t b[4][2];
#pragma unroll
            for (int pair = 0; pair < 2; pair++) {
                int ntile = pair * 2 + (g >> 1);
                uint32_t addr = bBase + (uint32_t)((ntile * 8 + r8) * PAD_BYTES
                                                  + ks * 32 + (g & 1) * 16);
                ldsm_x4(b[pair * 2][0], b[pair * 2][1], b[pair * 2 + 1][0], b[pair * 2 + 1][1], addr);
            }
#pragma unroll
            for (int mt = 0; mt < 4; mt++)
#pragma unroll
                for (int nt = 0; nt < 4; nt++)
                    mma_s8(c[mt][nt], a[mt][0], a[mt][1], a[mt][2], a[mt][3],
                           b[nt][0], b[nt][1]);
        }
        __syncthreads();
    }

    // ---------------- epilogue ----------------
    float dsa = fabsf(ds[0]);
    // per-nt column dequant scales (cols col, col+1)
    float pS[4][2];
#pragma unroll
    for (int nt = 0; nt < 4; nt++) {
        int col = n0 + wn * 32 + nt * 8 + 2 * (l & 3);
        pS[nt][0] = __ldg(&g_Ps[col]);
        pS[nt][1] = __ldg(&g_Ps[col + 1]);
    }
    float rs[4][2];
#pragma unroll
    for (int mt = 0; mt < 4; mt++) { rs[mt][0] = 0.0f; rs[mt][1] = 0.0f; }

#pragma unroll
    for (int mt = 0; mt < 4; mt++) {
        int mrow = m0 + wm * 64 + mt * 16 + (l >> 2);
        float fS0 = __ldg(&g_Fs[mrow]);
        float fS1 = __ldg(&g_Fs[mrow + 8]);
#pragma unroll
        for (int nt = 0; nt < 4; nt++) {
            int col = n0 + wn * 32 + nt * 8 + 2 * (l & 3);
            float s0 = (float)c[mt][nt][0] * fS0 * pS[nt][0];
            float s1 = (float)c[mt][nt][1] * fS0 * pS[nt][1];
            float s2 = (float)c[mt][nt][2] * fS1 * pS[nt][0];
            float s3 = (float)c[mt][nt][3] * fS1 * pS[nt][1];
            float i0 = dsa * sqrtf(fmaxf(1.0f - s0, 0.0f));
            float i1 = dsa * sqrtf(fmaxf(1.0f - s1, 0.0f));
            float i2 = dsa * sqrtf(fmaxf(1.0f - s2, 0.0f));
            float i3 = dsa * sqrtf(fmaxf(1.0f - s3, 0.0f));
            if (col < C_COLS) {             // col even, C_COLS even -> col+1 valid too
                rs[mt][0] += i0 + i1;
                rs[mt][1] += i2 + i3;
                float2 v01 = make_float2(i0, i1);
                float2 v23 = make_float2(i2, i3);
                *(float2*)(out + (size_t)mrow * C_COLS + col) = v01;
                *(float2*)(out + (size_t)(mrow + 8) * C_COLS + col) = v23;
            }
        }
    }
    // reduce row sums over the 4 lanes sharing a row (xor 1, 2), then atomics
#pragma unroll
    for (int mt = 0; mt < 4; mt++) {
#pragma unroll
        for (int h = 0; h < 2; h++) {
            float v = rs[mt][h];
            v += __shfl_xor_sync(0xffffffffu, v, 1);
            v += __shfl_xor_sync(0xffffffffu, v, 2);
            if ((l & 3) == 0) {
                int mrow = m0 + wm * 64 + mt * 16 + (l >> 2) + h * 8;
                atomicAdd(&g_rowsum[mrow], v);
            }
        }
    }
}

// ---------------------------------------------------------------------------
// Kernel 4: logits = -(iso + rowmean) / temperature, flat float4 grid.
// ---------------------------------------------------------------------------
#define F4_PER_ROW (C_COLS / 4)              // 250
#define FIN_TOTAL  (B_ROWS * F4_PER_ROW)     // 4,096,000

__global__ void __launch_bounds__(256) finalize_kernel(float* __restrict__ out,
                                                       const float* __restrict__ temp) {
    unsigned v = blockIdx.x * 256u + threadIdx.x;
    if (v >= (unsigned)FIN_TOTAL) return;
    unsigned row = v / (unsigned)F4_PER_ROW;
    float m = __ldg(&g_rowsum[row]) * (1.0f / (float)C_COLS);
    float invt = 1.0f / __ldg(temp);
    float4 x = *(float4*)(out + (size_t)v * 4);
    x.x = -(x.x + m) * invt;
    x.y = -(x.y + m) * invt;
    x.z = -(x.z + m) * invt;
    x.w = -(x.w + m) * invt;
    *(float4*)(out + (size_t)v * 4) = x;
}

// ---------------------------------------------------------------------------
extern "C" void kernel_launch(void* const* d_in, const int* in_sizes, int n_in,
                              void* d_out, int out_size) {
    const float* feat = (const float*)d_in[0];
    const float* prot = (const float*)d_in[1];
    const float* ds   = (const float*)d_in[2];
    const float* temp = (const float*)d_in[3];
    float* out = (float*)d_out;

    cudaFuncSetAttribute(gemm_kernel, cudaFuncAttributeMaxDynamicSharedMemorySize, GEMM_SMEM);

    norm_features_kernel<<<B_ROWS, 256>>>(feat);
    norm_protos_kernel<<<C_PAD, 256>>>(prot);
    gemm_kernel<<<dim3(C_PAD / 128, B_ROWS / 128), 256, GEMM_SMEM>>>(ds, out);
    finalize_kernel<<<(FIN_TOTAL + 255) / 256, 256>>>(out, temp);
}

// round 8
// speedup vs baseline: 1.3883x; 1.3883x over previous
#include <cuda_runtime.h>
#include <cuda_bf16.h>
#include <cstdint>

#define B_ROWS 16384
#define F_DIM  1024
#define C_COLS 1000
#define C_PAD  1024

// Scratch (static __device__ arrays allowed; no dynamic allocation)
__device__ __nv_bfloat16 g_Fb[(size_t)B_ROWS * F_DIM];   // normalized features, bf16
__device__ __nv_bfloat16 g_Pb[(size_t)C_PAD * F_DIM];    // normalized prototypes (padded), bf16

// ---------------------------------------------------------------------------
// Helpers (base-ISA only: cp.async, ldmatrix, bf16 mma.sync — ptxas target is
// plain sm_103, no 'a' features / tcgen05)
// ---------------------------------------------------------------------------
__device__ __forceinline__ uint32_t smem_u32(const void* p) {
    uint32_t a;
    asm("{ .reg .u64 t; cvta.to.shared.u64 t, %1; cvt.u32.u64 %0, t; }" : "=r"(a) : "l"(p));
    return a;
}
__device__ __forceinline__ void cp_async16(uint32_t dst, const void* src) {
    asm volatile("cp.async.cg.shared.global [%0], [%1], 16;" :: "r"(dst), "l"(src));
}
__device__ __forceinline__ void cp_commit() { asm volatile("cp.async.commit_group;" ::: "memory"); }

__device__ __forceinline__ void ldsm_x4(uint32_t& r0, uint32_t& r1, uint32_t& r2, uint32_t& r3,
                                        uint32_t addr) {
    asm volatile("ldmatrix.sync.aligned.m8n8.x4.shared.b16 {%0,%1,%2,%3}, [%4];"
                 : "=r"(r0), "=r"(r1), "=r"(r2), "=r"(r3) : "r"(addr));
}
__device__ __forceinline__ void mma_bf16(float* c, uint32_t a0, uint32_t a1, uint32_t a2,
                                         uint32_t a3, uint32_t b0, uint32_t b1) {
    asm volatile(
        "mma.sync.aligned.m16n8k16.row.col.f32.bf16.bf16.f32 "
        "{%0,%1,%2,%3}, {%4,%5,%6,%7}, {%8,%9}, {%0,%1,%2,%3};"
        : "+f"(c[0]), "+f"(c[1]), "+f"(c[2]), "+f"(c[3])
        : "r"(a0), "r"(a1), "r"(a2), "r"(a3), "r"(b0), "r"(b1));
}

// ---------------------------------------------------------------------------
// Kernels 1/2: L2-normalize rows -> bf16
// ---------------------------------------------------------------------------
__global__ void __launch_bounds__(256) norm_features_kernel(const float* __restrict__ in) {
    int row = blockIdx.x, tid = threadIdx.x;
    const float4* rin = (const float4*)(in + (size_t)row * F_DIM);
    float4 v = rin[tid];
    float ss = v.x * v.x + v.y * v.y + v.z * v.z + v.w * v.w;
#pragma unroll
    for (int o = 16; o; o >>= 1) ss += __shfl_xor_sync(0xffffffffu, ss, o);
    __shared__ float red[8];
    if ((tid & 31) == 0) red[tid >> 5] = ss;
    __syncthreads();
    if (tid < 8) {
        float t = red[tid];
#pragma unroll
        for (int o = 4; o; o >>= 1) t += __shfl_xor_sync(0x000000ffu, t, o);
        if (tid == 0) red[0] = t;
    }
    __syncthreads();
    float sc = 1.0f / fmaxf(sqrtf(red[0]), 1e-12f);
    __nv_bfloat162* dst = (__nv_bfloat162*)(g_Fb + (size_t)row * F_DIM);
    dst[tid * 2 + 0] = __floats2bfloat162_rn(v.x * sc, v.y * sc);
    dst[tid * 2 + 1] = __floats2bfloat162_rn(v.z * sc, v.w * sc);
}

__global__ void __launch_bounds__(256) norm_protos_kernel(const float* __restrict__ in) {
    int row = blockIdx.x, tid = threadIdx.x;
    __nv_bfloat162* dst = (__nv_bfloat162*)(g_Pb + (size_t)row * F_DIM);
    if (row >= C_COLS) {
        __nv_bfloat162 z = __floats2bfloat162_rn(0.f, 0.f);
        dst[tid * 2 + 0] = z;
        dst[tid * 2 + 1] = z;
        return;
    }
    const float4* rin = (const float4*)(in + (size_t)row * F_DIM);
    float4 v = rin[tid];
    float ss = v.x * v.x + v.y * v.y + v.z * v.z + v.w * v.w;
#pragma unroll
    for (int o = 16; o; o >>= 1) ss += __shfl_xor_sync(0xffffffffu, ss, o);
    __shared__ float red[8];
    if ((tid & 31) == 0) red[tid >> 5] = ss;
    __syncthreads();
    if (tid < 8) {
        float t = red[tid];
#pragma unroll
        for (int o = 4; o; o >>= 1) t += __shfl_xor_sync(0x000000ffu, t, o);
        if (tid == 0) red[0] = t;
    }
    __syncthreads();
    float sc = 1.0f / fmaxf(sqrtf(red[0]), 1e-12f);
    dst[tid * 2 + 0] = __floats2bfloat162_rn(v.x * sc, v.y * sc);
    dst[tid * 2 + 1] = __floats2bfloat162_rn(v.z * sc, v.w * sc);
}

// ---------------------------------------------------------------------------
// Kernel 3: fused bf16 GEMM + finalize.
// Each CTA owns a 64-row strip x all 1024 cols: 8 n-tiles x 16 k-chunks,
// 3-stage cp.async pipeline over the flattened (ntile, kc) index.
// 8 warps: wm = wid>>2 (0..1, 32 rows each), wn = wid&3 (0..3, 32 cols each).
// Pass 1 (per n-tile epilogue): iso = |ds|*sqrt(max(1-sim,0)) -> out; row sums
// accumulate in SMEM. Pass 2 (in-kernel): out = -(iso + rowmean)/T, re-reading
// the CTA's own L2-hot strip. No global atomics, no separate finalize kernel.
// ---------------------------------------------------------------------------
#define MSTRIP  64
#define STAGES  3
#define BK      64                         // bf16 elements per k-chunk (128B)
#define KCHUNKS (F_DIM / BK)               // 16
#define NTILES  (C_PAD / 128)              // 8
#define T_TOTAL (NTILES * KCHUNKS)         // 128
#define PAD_BYTES 144                      // 128B data + 16B pad per row
#define A_SZ (MSTRIP * PAD_BYTES)          // 9216
#define B_SZ (128 * PAD_BYTES)             // 18432
#define STAGE_BYTES (A_SZ + B_SZ)          // 27648
#define GEMM_SMEM (STAGES * STAGE_BYTES + 256)   // 83200 -> 2 CTAs/SM

__device__ __forceinline__ void load_tile(uint32_t base, int t, int m0, int tid) {
    int nt = t >> 4, kc = t & 15;
    const char* fb = (const char*)g_Fb;
    const char* pb = (const char*)g_Pb;
    uint32_t st = base + (uint32_t)(t % STAGES) * STAGE_BYTES;
    // A: 64 rows x 128B  -> 512 x 16B ops, 2 per thread
#pragma unroll
    for (int it = 0; it < 2; it++) {
        int s = tid + it * 256;            // 0..511
        int r = s >> 3, q = s & 7;
        cp_async16(st + (uint32_t)(r * PAD_BYTES + q * 16),
                   fb + (size_t)(m0 + r) * 2048 + (size_t)kc * 128 + q * 16);
    }
    // B: 128 rows x 128B -> 1024 x 16B ops, 4 per thread
    uint32_t stB = st + A_SZ;
#pragma unroll
    for (int it = 0; it < 4; it++) {
        int s = tid + it * 256;
        int r = s >> 3, q = s & 7;
        cp_async16(stB + (uint32_t)(r * PAD_BYTES + q * 16),
                   pb + (size_t)(nt * 128 + r) * 2048 + (size_t)kc * 128 + q * 16);
    }
    cp_commit();
}

__global__ void __launch_bounds__(256, 2) gemm_kernel(const float* __restrict__ ds,
                                                      const float* __restrict__ temp,
                                                      float* __restrict__ out) {
    extern __shared__ char smem_raw[];
    uint32_t base = smem_u32(smem_raw);
    float* srow = (float*)(smem_raw + STAGES * STAGE_BYTES);   // 64 row sums

    int tid = threadIdx.x;
    int wid = tid >> 5, l = tid & 31;
    int wm = wid >> 2, wn = wid & 3;
    int m0 = blockIdx.x * MSTRIP;

    if (tid < MSTRIP) srow[tid] = 0.0f;

    float dsa = fabsf(__ldg(ds));
    float c[2][4][4];
    float rs[2][2];
    rs[0][0] = rs[0][1] = rs[1][0] = rs[1][1] = 0.0f;

    int g = l >> 3;          // 0..3
    int r8 = l & 7;

    // prologue: prefetch tiles 0, 1
    load_tile(base, 0, m0, tid);
    load_tile(base, 1, m0, tid);

    for (int t = 0; t < T_TOTAL; t++) {
        if (t < T_TOTAL - 1) asm volatile("cp.async.wait_group 1;" ::: "memory");
        else                 asm volatile("cp.async.wait_group 0;" ::: "memory");
        __syncthreads();

        if (t + 2 < T_TOTAL) load_tile(base, t + 2, m0, tid);

        int kc = t & 15;
        if (kc == 0) {
#pragma unroll
            for (int i = 0; i < 2; i++)
#pragma unroll
                for (int j = 0; j < 4; j++)
#pragma unroll
                    for (int k = 0; k < 4; k++) c[i][j][k] = 0.0f;
        }

        uint32_t st = base + (uint32_t)(t % STAGES) * STAGE_BYTES;
        uint32_t aBase = st + (uint32_t)(wm * 32) * PAD_BYTES;
        uint32_t bBase = st + A_SZ + (uint32_t)(wn * 32) * PAD_BYTES;

#pragma unroll
        for (int ks = 0; ks < 4; ks++) {
            uint32_t a[2][4];
#pragma unroll
            for (int mt = 0; mt < 2; mt++) {
                uint32_t addr = aBase + (uint32_t)((mt * 16 + (g & 1) * 8 + r8) * PAD_BYTES
                                                  + ks * 32 + (g >> 1) * 16);
                ldsm_x4(a[mt][0], a[mt][1], a[mt][2], a[mt][3], addr);
            }
            uint32_t b[4][2];
#pragma unroll
            for (int pair = 0; pair < 2; pair++) {
                int ntile = pair * 2 + (g >> 1);
                uint32_t addr = bBase + (uint32_t)((ntile * 8 + r8) * PAD_BYTES
                                                  + ks * 32 + (g & 1) * 16);
                ldsm_x4(b[pair * 2][0], b[pair * 2][1], b[pair * 2 + 1][0], b[pair * 2 + 1][1], addr);
            }
#pragma unroll
            for (int mt = 0; mt < 2; mt++)
#pragma unroll
                for (int nt2 = 0; nt2 < 4; nt2++)
                    mma_bf16(c[mt][nt2], a[mt][0], a[mt][1], a[mt][2], a[mt][3],
                             b[nt2][0], b[nt2][1]);
        }

        // ---- per-ntile epilogue (pass 1) ----
        if (kc == 15) {
            int n0 = (t >> 4) * 128;
#pragma unroll
            for (int mt = 0; mt < 2; mt++) {
                int mrow = m0 + wm * 32 + mt * 16 + (l >> 2);
#pragma unroll
                for (int nt2 = 0; nt2 < 4; nt2++) {
                    int col = n0 + wn * 32 + nt2 * 8 + 2 * (l & 3);
                    float i0 = dsa * sqrtf(fmaxf(1.0f - c[mt][nt2][0], 0.0f));
                    float i1 = dsa * sqrtf(fmaxf(1.0f - c[mt][nt2][1], 0.0f));
                    float i2 = dsa * sqrtf(fmaxf(1.0f - c[mt][nt2][2], 0.0f));
                    float i3 = dsa * sqrtf(fmaxf(1.0f - c[mt][nt2][3], 0.0f));
                    if (col < C_COLS) {    // col even, C_COLS even -> col+1 valid
                        rs[mt][0] += i0 + i1;
                        rs[mt][1] += i2 + i3;
                        *(float2*)(out + (size_t)mrow * C_COLS + col) = make_float2(i0, i1);
                        *(float2*)(out + (size_t)(mrow + 8) * C_COLS + col) = make_float2(i2, i3);
                    }
                }
            }
        }
        __syncthreads();
    }

    // ---- reduce row sums into SMEM ----
#pragma unroll
    for (int mt = 0; mt < 2; mt++) {
#pragma unroll
        for (int h = 0; h < 2; h++) {
            float v = rs[mt][h];
            v += __shfl_xor_sync(0xffffffffu, v, 1);
            v += __shfl_xor_sync(0xffffffffu, v, 2);
            if ((l & 3) == 0) {
                int lr = wm * 32 + mt * 16 + (l >> 2) + h * 8;   // 0..63
                atomicAdd(&srow[lr], v);
            }
        }
    }
    __syncthreads();

    // ---- pass 2: out = -(iso + rowmean) / T on this CTA's (L2-hot) strip ----
    float invt = 1.0f / __ldg(temp);
#pragma unroll 4
    for (int i = tid; i < MSTRIP * (C_COLS / 4); i += 256) {
        int row = i / (C_COLS / 4);
        int c4  = i - row * (C_COLS / 4);
        float m = srow[row] * (1.0f / (float)C_COLS);
        float4* p = (float4*)(out + (size_t)(m0 + row) * C_COLS) + c4;
        float4 x = *p;
        x.x = -(x.x + m) * invt;
        x.y = -(x.y + m) * invt;
        x.z = -(x.z + m) * invt;
        x.w = -(x.w + m) * invt;
        *p = x;
    }
}

// ---------------------------------------------------------------------------
extern "C" void kernel_launch(void* const* d_in, const int* in_sizes, int n_in,
                              void* d_out, int out_size) {
    const float* feat = (const float*)d_in[0];
    const float* prot = (const float*)d_in[1];
    const float* ds   = (const float*)d_in[2];
    const float* temp = (const float*)d_in[3];
    float* out = (float*)d_out;

    cudaFuncSetAttribute(gemm_kernel, cudaFuncAttributeMaxDynamicSharedMemorySize, GEMM_SMEM);

    norm_features_kernel<<<B_ROWS, 256>>>(feat);
    norm_protos_kernel<<<C_PAD, 256>>>(prot);
    gemm_kernel<<<B_ROWS / MSTRIP, 256, GEMM_SMEM>>>(ds, temp, out);
}

// round 11
// speedup vs baseline: 1.6013x; 1.1534x over previous
#include <cuda_runtime.h>
#include <cuda_bf16.h>
#include <cstdint>

#define B_ROWS 16384
#define F_DIM  1024
#define C_COLS 1000
#define C_PAD  1024

// Scratch (static __device__ arrays allowed; no dynamic allocation)
__device__ __nv_bfloat16 g_Fb[(size_t)B_ROWS * F_DIM];   // normalized features, bf16
__device__ __nv_bfloat16 g_Pb[(size_t)C_PAD * F_DIM];    // normalized prototypes (padded), bf16
__device__ float g_rowsum[B_ROWS];

// ---------------------------------------------------------------------------
// Helpers (base-ISA only: cp.async, ldmatrix, bf16 mma.sync)
// ---------------------------------------------------------------------------
__device__ __forceinline__ uint32_t smem_u32(const void* p) {
    uint32_t a;
    asm("{ .reg .u64 t; cvta.to.shared.u64 t, %1; cvt.u32.u64 %0, t; }" : "=r"(a) : "l"(p));
    return a;
}
__device__ __forceinline__ void cp_async16(uint32_t dst, const void* src) {
    asm volatile("cp.async.cg.shared.global [%0], [%1], 16;" :: "r"(dst), "l"(src));
}
__device__ __forceinline__ void cp_commit() { asm volatile("cp.async.commit_group;" ::: "memory"); }

__device__ __forceinline__ void ldsm_x4(uint32_t& r0, uint32_t& r1, uint32_t& r2, uint32_t& r3,
                                        uint32_t addr) {
    asm volatile("ldmatrix.sync.aligned.m8n8.x4.shared.b16 {%0,%1,%2,%3}, [%4];"
                 : "=r"(r0), "=r"(r1), "=r"(r2), "=r"(r3) : "r"(addr));
}
__device__ __forceinline__ void mma_bf16(float* c, uint32_t a0, uint32_t a1, uint32_t a2,
                                         uint32_t a3, uint32_t b0, uint32_t b1) {
    asm volatile(
        "mma.sync.aligned.m16n8k16.row.col.f32.bf16.bf16.f32 "
        "{%0,%1,%2,%3}, {%4,%5,%6,%7}, {%8,%9}, {%0,%1,%2,%3};"
        : "+f"(c[0]), "+f"(c[1]), "+f"(c[2]), "+f"(c[3])
        : "r"(a0), "r"(a1), "r"(a2), "r"(a3), "r"(b0), "r"(b1));
}

// ---------------------------------------------------------------------------
// Kernels 1/2: L2-normalize rows -> bf16
// ---------------------------------------------------------------------------
__global__ void __launch_bounds__(256) norm_features_kernel(const float* __restrict__ in) {
    int row = blockIdx.x, tid = threadIdx.x;
    const float4* rin = (const float4*)(in + (size_t)row * F_DIM);
    float4 v = rin[tid];
    float ss = v.x * v.x + v.y * v.y + v.z * v.z + v.w * v.w;
#pragma unroll
    for (int o = 16; o; o >>= 1) ss += __shfl_xor_sync(0xffffffffu, ss, o);
    __shared__ float red[8];
    if ((tid & 31) == 0) red[tid >> 5] = ss;
    __syncthreads();
    if (tid < 8) {
        float t = red[tid];
#pragma unroll
        for (int o = 4; o; o >>= 1) t += __shfl_xor_sync(0x000000ffu, t, o);
        if (tid == 0) red[0] = t;
    }
    __syncthreads();
    float sc = 1.0f / fmaxf(sqrtf(red[0]), 1e-12f);
    __nv_bfloat162* dst = (__nv_bfloat162*)(g_Fb + (size_t)row * F_DIM);
    dst[tid * 2 + 0] = __floats2bfloat162_rn(v.x * sc, v.y * sc);
    dst[tid * 2 + 1] = __floats2bfloat162_rn(v.z * sc, v.w * sc);
    if (tid == 0) g_rowsum[row] = 0.0f;
}

__global__ void __launch_bounds__(256) norm_protos_kernel(const float* __restrict__ in) {
    int row = blockIdx.x, tid = threadIdx.x;
    __nv_bfloat162* dst = (__nv_bfloat162*)(g_Pb + (size_t)row * F_DIM);
    if (row >= C_COLS) {
        __nv_bfloat162 z = __floats2bfloat162_rn(0.f, 0.f);
        dst[tid * 2 + 0] = z;
        dst[tid * 2 + 1] = z;
        return;
    }
    const float4* rin = (const float4*)(in + (size_t)row * F_DIM);
    float4 v = rin[tid];
    float ss = v.x * v.x + v.y * v.y + v.z * v.z + v.w * v.w;
#pragma unroll
    for (int o = 16; o; o >>= 1) ss += __shfl_xor_sync(0xffffffffu, ss, o);
    __shared__ float red[8];
    if ((tid & 31) == 0) red[tid >> 5] = ss;
    __syncthreads();
    if (tid < 8) {
        float t = red[tid];
#pragma unroll
        for (int o = 4; o; o >>= 1) t += __shfl_xor_sync(0x000000ffu, t, o);
        if (tid == 0) red[0] = t;
    }
    __syncthreads();
    float sc = 1.0f / fmaxf(sqrtf(red[0]), 1e-12f);
    dst[tid * 2 + 0] = __floats2bfloat162_rn(v.x * sc, v.y * sc);
    dst[tid * 2 + 1] = __floats2bfloat162_rn(v.z * sc, v.w * sc);
}

// ---------------------------------------------------------------------------
// Kernel 3: bf16 mma.sync GEMM, CTA 128(M)x256(N), BK=64, 3-stage pipeline.
// 8 warps 2x4, warp tile 64x64 (per ks: 8 ldsm -> 32 mma, 16 MAC/smem-byte).
// 1 CTA/SM (~180 regs/thread). Epilogue: iso + row-sum atomics (R4-style).
// ---------------------------------------------------------------------------
#define STAGES 3
#define BK 64
#define KCHUNKS (F_DIM / BK)           // 16
#define PAD_BYTES 144                  // (64+8) bf16 per row
#define A_SZ (128 * PAD_BYTES)         // 18432
#define B_SZ (256 * PAD_BYTES)         // 36864
#define STAGE_BYTES (A_SZ + B_SZ)      // 55296
#define GEMM_SMEM (STAGES * STAGE_BYTES)   // 165888

__device__ __forceinline__ void load_tile(uint32_t base, int kc, int m0, int n0, int tid) {
    const char* fb = (const char*)g_Fb;
    const char* pb = (const char*)g_Pb;
    uint32_t st = base + (uint32_t)(kc % STAGES) * STAGE_BYTES;
    // A: 128 rows x 128B -> 1024 x 16B, 4 per thread
#pragma unroll
    for (int it = 0; it < 4; it++) {
        int s = tid + it * 256;
        int r = s >> 3, q = s & 7;
        cp_async16(st + (uint32_t)(r * PAD_BYTES + q * 16),
                   fb + (size_t)(m0 + r) * 2048 + (size_t)kc * 128 + q * 16);
    }
    // B: 256 rows x 128B -> 2048 x 16B, 8 per thread
    uint32_t stB = st + A_SZ;
#pragma unroll
    for (int it = 0; it < 8; it++) {
        int s = tid + it * 256;
        int r = s >> 3, q = s & 7;
        cp_async16(stB + (uint32_t)(r * PAD_BYTES + q * 16),
                   pb + (size_t)(n0 + r) * 2048 + (size_t)kc * 128 + q * 16);
    }
    cp_commit();
}

__global__ void __launch_bounds__(256, 1) gemm_kernel(const float* __restrict__ ds,
                                                      float* __restrict__ out) {
    extern __shared__ char smem_raw[];
    uint32_t base = smem_u32(smem_raw);

    int tid = threadIdx.x;
    int wid = tid >> 5, l = tid & 31;
    int wm = wid >> 2, wn = wid & 3;          // wm: 64-row half, wn: 64-col quarter
    int m0 = blockIdx.y * 128, n0 = blockIdx.x * 256;

    float c[4][8][4];
#pragma unroll
    for (int i = 0; i < 4; i++)
#pragma unroll
        for (int j = 0; j < 8; j++)
#pragma unroll
            for (int k = 0; k < 4; k++) c[i][j][k] = 0.0f;

    int g = l >> 3;          // 0..3
    int r8 = l & 7;

    // prologue: prefetch chunks 0, 1
    load_tile(base, 0, m0, n0, tid);
    load_tile(base, 1, m0, n0, tid);

    for (int kc = 0; kc < KCHUNKS; kc++) {
        if (kc < KCHUNKS - 1) asm volatile("cp.async.wait_group 1;" ::: "memory");
        else                  asm volatile("cp.async.wait_group 0;" ::: "memory");
        __syncthreads();

        if (kc + 2 < KCHUNKS) load_tile(base, kc + 2, m0, n0, tid);

        uint32_t st = base + (uint32_t)(kc % STAGES) * STAGE_BYTES;
        uint32_t aBase = st + (uint32_t)(wm * 64) * PAD_BYTES;
        uint32_t bBase = st + A_SZ + (uint32_t)(wn * 64) * PAD_BYTES;

#pragma unroll
        for (int ks = 0; ks < 4; ks++) {
            uint32_t a[4][4];
#pragma unroll
            for (int mt = 0; mt < 4; mt++) {
                // lanes: g0 rows 0-7 k-lo | g1 rows 8-15 k-lo | g2 rows 0-7 k-hi | g3 rows 8-15 k-hi
                uint32_t addr = aBase + (uint32_t)((mt * 16 + (g & 1) * 8 + r8) * PAD_BYTES
                                                  + ks * 32 + (g >> 1) * 16);
                ldsm_x4(a[mt][0], a[mt][1], a[mt][2], a[mt][3], addr);
            }
            uint32_t b[8][2];
#pragma unroll
            for (int pair = 0; pair < 4; pair++) {
                // matrices: [ntile 2p, k-lo] [ntile 2p, k-hi] [ntile 2p+1, k-lo] [ntile 2p+1, k-hi]
                int ntile = pair * 2 + (g >> 1);
                uint32_t addr = bBase + (uint32_t)((ntile * 8 + r8) * PAD_BYTES
                                                  + ks * 32 + (g & 1) * 16);
                ldsm_x4(b[pair * 2][0], b[pair * 2][1], b[pair * 2 + 1][0], b[pair * 2 + 1][1], addr);
            }
#pragma unroll
            for (int mt = 0; mt < 4; mt++)
#pragma unroll
                for (int nt = 0; nt < 8; nt++)
                    mma_bf16(c[mt][nt], a[mt][0], a[mt][1], a[mt][2], a[mt][3],
                             b[nt][0], b[nt][1]);
        }
        __syncthreads();
    }

    // ---------------- epilogue ----------------
    float dsa = fabsf(__ldg(ds));
    float rs[4][2];
#pragma unroll
    for (int mt = 0; mt < 4; mt++) { rs[mt][0] = 0.0f; rs[mt][1] = 0.0f; }

#pragma unroll
    for (int mt = 0; mt < 4; mt++) {
        int mrow = m0 + wm * 64 + mt * 16 + (l >> 2);
#pragma unroll
        for (int nt = 0; nt < 8; nt++) {
            int col = n0 + wn * 64 + nt * 8 + 2 * (l & 3);
            float i0 = dsa * sqrtf(fmaxf(1.0f - c[mt][nt][0], 0.0f));
            float i1 = dsa * sqrtf(fmaxf(1.0f - c[mt][nt][1], 0.0f));
            float i2 = dsa * sqrtf(fmaxf(1.0f - c[mt][nt][2], 0.0f));
            float i3 = dsa * sqrtf(fmaxf(1.0f - c[mt][nt][3], 0.0f));
            if (col < C_COLS) {             // col even, C_COLS even -> col+1 valid too
                rs[mt][0] += i0 + i1;
                rs[mt][1] += i2 + i3;
                *(float2*)(out + (size_t)mrow * C_COLS + col) = make_float2(i0, i1);
                *(float2*)(out + (size_t)(mrow + 8) * C_COLS + col) = make_float2(i2, i3);
            }
        }
    }
    // reduce row sums over the 4 lanes sharing a row (xor 1, 2), then atomics
#pragma unroll
    for (int mt = 0; mt < 4; mt++) {
#pragma unroll
        for (int h = 0; h < 2; h++) {
            float v = rs[mt][h];
            v += __shfl_xor_sync(0xffffffffu, v, 1);
            v += __shfl_xor_sync(0xffffffffu, v, 2);
            if ((l & 3) == 0) {
                int mrow = m0 + wm * 64 + mt * 16 + (l >> 2) + h * 8;
                atomicAdd(&g_rowsum[mrow], v);
            }
        }
    }
}

// ---------------------------------------------------------------------------
// Kernel 4: logits = -(iso + rowmean) / temperature, flat float4 grid.
// ---------------------------------------------------------------------------
#define F4_PER_ROW (C_COLS / 4)              // 250
#define FIN_TOTAL  (B_ROWS * F4_PER_ROW)     // 4,096,000

__global__ void __launch_bounds__(256) finalize_kernel(float* __restrict__ out,
                                                       const float* __restrict__ temp) {
    unsigned v = blockIdx.x * 256u + threadIdx.x;
    if (v >= (unsigned)FIN_TOTAL) return;
    unsigned row = v / (unsigned)F4_PER_ROW;
    float m = __ldg(&g_rowsum[row]) * (1.0f / (float)C_COLS);
    float invt = 1.0f / __ldg(temp);
    float4 x = *(float4*)(out + (size_t)v * 4);
    x.x = -(x.x + m) * invt;
    x.y = -(x.y + m) * invt;
    x.z = -(x.z + m) * invt;
    x.w = -(x.w + m) * invt;
    *(float4*)(out + (size_t)v * 4) = x;
}

// ---------------------------------------------------------------------------
extern "C" void kernel_launch(void* const* d_in, const int* in_sizes, int n_in,
                              void* d_out, int out_size) {
    const float* feat = (const float*)d_in[0];
    const float* prot = (const float*)d_in[1];
    const float* ds   = (const float*)d_in[2];
    const float* temp = (const float*)d_in[3];
    float* out = (float*)d_out;

    cudaFuncSetAttribute(gemm_kernel, cudaFuncAttributeMaxDynamicSharedMemorySize, GEMM_SMEM);

    norm_features_kernel<<<B_ROWS, 256>>>(feat);
    norm_protos_kernel<<<C_PAD, 256>>>(prot);
    gemm_kernel<<<dim3(C_PAD / 256, B_ROWS / 128), 256, GEMM_SMEM>>>(ds, out);
    finalize_kernel<<<(FIN_TOTAL + 255) / 256, 256>>>(out, temp);
}

// round 13
// speedup vs baseline: 2.0613x; 1.2873x over previous
#include <cuda_runtime.h>
#include <cuda_bf16.h>
#include <cstdint>

#define B_ROWS 16384
#define F_DIM  1024
#define C_COLS 1000
#define C_PAD  1024

// Scratch (static __device__ arrays allowed; no dynamic allocation)
__device__ __nv_bfloat16 g_Fb[(size_t)B_ROWS * F_DIM];   // normalized features, bf16
__device__ __nv_bfloat16 g_Pb[(size_t)C_PAD * F_DIM];    // normalized prototypes (padded), bf16
__device__ float g_rowsum[B_ROWS];

// ---------------------------------------------------------------------------
// Helpers (base-ISA only: cp.async, ldmatrix, bf16 mma.sync)
// ---------------------------------------------------------------------------
__device__ __forceinline__ uint32_t smem_u32(const void* p) {
    uint32_t a;
    asm("{ .reg .u64 t; cvta.to.shared.u64 t, %1; cvt.u32.u64 %0, t; }" : "=r"(a) : "l"(p));
    return a;
}
__device__ __forceinline__ void cp_async16(uint32_t dst, const void* src) {
    asm volatile("cp.async.cg.shared.global [%0], [%1], 16;" :: "r"(dst), "l"(src));
}
__device__ __forceinline__ void cp_commit() { asm volatile("cp.async.commit_group;" ::: "memory"); }

__device__ __forceinline__ void ldsm_x4(uint32_t& r0, uint32_t& r1, uint32_t& r2, uint32_t& r3,
                                        uint32_t addr) {
    asm volatile("ldmatrix.sync.aligned.m8n8.x4.shared.b16 {%0,%1,%2,%3}, [%4];"
                 : "=r"(r0), "=r"(r1), "=r"(r2), "=r"(r3) : "r"(addr));
}
__device__ __forceinline__ void mma_bf16(float* c, uint32_t a0, uint32_t a1, uint32_t a2,
                                         uint32_t a3, uint32_t b0, uint32_t b1) {
    asm volatile(
        "mma.sync.aligned.m16n8k16.row.col.f32.bf16.bf16.f32 "
        "{%0,%1,%2,%3}, {%4,%5,%6,%7}, {%8,%9}, {%0,%1,%2,%3};"
        : "+f"(c[0]), "+f"(c[1]), "+f"(c[2]), "+f"(c[3])
        : "r"(a0), "r"(a1), "r"(a2), "r"(a3), "r"(b0), "r"(b1));
}
__device__ __forceinline__ uint32_t packbf2(float lo, float hi) {
    __nv_bfloat162 h = __floats2bfloat162_rn(lo, hi);
    return *reinterpret_cast<uint32_t*>(&h);
}

// ---------------------------------------------------------------------------
// Kernel 1: merged L2-normalize (features then protos), one WARP per row.
// 8 float4 loads/lane (MLP=8), shuffle-only reduction, uint2 bf16 stores.
// ---------------------------------------------------------------------------
#define NORM_ROWS (B_ROWS + C_PAD)           // 17408
__global__ void __launch_bounds__(256) norm_kernel(const float* __restrict__ feat,
                                                   const float* __restrict__ prot) {
    int gw = blockIdx.x * 8 + (threadIdx.x >> 5);
    int l = threadIdx.x & 31;

    const float* src;
    uint2* dst;
    if (gw < B_ROWS) {
        src = feat + (size_t)gw * F_DIM;
        dst = (uint2*)(g_Fb + (size_t)gw * F_DIM);
    } else {
        int row = gw - B_ROWS;               // 0..1023
        dst = (uint2*)(g_Pb + (size_t)row * F_DIM);
        if (row >= C_COLS) {                 // zero padding rows
            uint2 z = make_uint2(0u, 0u);
#pragma unroll
            for (int i = 0; i < 8; i++) dst[l + 32 * i] = z;
            return;
        }
        src = prot + (size_t)row * F_DIM;
    }

    const float4* rin = (const float4*)src;
    float4 v[8];
    float ss = 0.0f;
#pragma unroll
    for (int i = 0; i < 8; i++) v[i] = rin[l + 32 * i];
#pragma unroll
    for (int i = 0; i < 8; i++)
        ss += v[i].x * v[i].x + v[i].y * v[i].y + v[i].z * v[i].z + v[i].w * v[i].w;
#pragma unroll
    for (int o = 16; o; o >>= 1) ss += __shfl_xor_sync(0xffffffffu, ss, o);

    float sc = 1.0f / fmaxf(sqrtf(ss), 1e-12f);
#pragma unroll
    for (int i = 0; i < 8; i++) {
        uint2 w2;
        w2.x = packbf2(v[i].x * sc, v[i].y * sc);
        w2.y = packbf2(v[i].z * sc, v[i].w * sc);
        dst[l + 32 * i] = w2;
    }
    if (gw < B_ROWS && l == 0) g_rowsum[gw] = 0.0f;
}

// ---------------------------------------------------------------------------
// Kernel 2: bf16 mma.sync GEMM, CTA 128x128, BK=64, 3-stage cp.async pipeline
// 110.6KB smem -> 2 CTAs/SM (16 warps/SM).
// 8 warps: wm = wid>>2 (0..1, 64 rows each), wn = wid&3 (0..3, 32 cols each)
// Epilogue: iso = |ds| * sqrt(max(1 - sim, 0)); direct store + row-sum atomics
// ---------------------------------------------------------------------------
#define STAGES 3
#define BK 64
#define KCHUNKS (F_DIM / BK)          // 16
#define PAD_BYTES 144                 // (64+8) bf16 per row
#define A_ST_BYTES (128 * PAD_BYTES)  // 18432
#define STAGE_BYTES (2 * A_ST_BYTES)  // 36864 (A then B)
#define GEMM_SMEM (STAGES * STAGE_BYTES)   // 110592 -> 2 CTAs/SM

__device__ __forceinline__ void load_tile(uint32_t base, int kc, int m0, int n0, int tid) {
    const char* fb = (const char*)g_Fb;
    const char* pb = (const char*)g_Pb;
    uint32_t st = base + (uint32_t)(kc % STAGES) * STAGE_BYTES;
#pragma unroll
    for (int it = 0; it < 4; it++) {
        int s = tid + it * 256;            // 0..1023
        int r = s >> 3, q = s & 7;
        cp_async16(st + (uint32_t)(r * PAD_BYTES + q * 16),
                   fb + (size_t)(m0 + r) * 2048 + (size_t)kc * 128 + q * 16);
    }
    uint32_t stB = st + A_ST_BYTES;
#pragma unroll
    for (int it = 0; it < 4; it++) {
        int s = tid + it * 256;
        int r = s >> 3, q = s & 7;
        cp_async16(stB + (uint32_t)(r * PAD_BYTES + q * 16),
                   pb + (size_t)(n0 + r) * 2048 + (size_t)kc * 128 + q * 16);
    }
    cp_commit();
}

__global__ void __launch_bounds__(256, 2) gemm_kernel(const float* __restrict__ ds,
                                                      float* __restrict__ out) {
    extern __shared__ char smem_raw[];
    uint32_t base = smem_u32(smem_raw);

    int tid = threadIdx.x;
    int wid = tid >> 5, l = tid & 31;
    int wm = wid >> 2, wn = wid & 3;
    int m0 = blockIdx.y * 128, n0 = blockIdx.x * 128;

    float c[4][4][4];
#pragma unroll
    for (int i = 0; i < 4; i++)
#pragma unroll
        for (int j = 0; j < 4; j++)
#pragma unroll
            for (int k = 0; k < 4; k++) c[i][j][k] = 0.0f;

    // prologue: prefetch chunks 0, 1
    load_tile(base, 0, m0, n0, tid);
    load_tile(base, 1, m0, n0, tid);

    for (int kc = 0; kc < KCHUNKS; kc++) {
        if (kc < KCHUNKS - 1) asm volatile("cp.async.wait_group 1;" ::: "memory");
        else                  asm volatile("cp.async.wait_group 0;" ::: "memory");
        __syncthreads();

        if (kc + 2 < KCHUNKS) load_tile(base, kc + 2, m0, n0, tid);

        uint32_t st = base + (uint32_t)(kc % STAGES) * STAGE_BYTES;
        uint32_t aBase = st + (uint32_t)(wm * 64) * PAD_BYTES;
        uint32_t bBase = st + A_ST_BYTES + (uint32_t)(wn * 32) * PAD_BYTES;

        int g = l >> 3;          // 0..3
        int r8 = l & 7;
#pragma unroll
        for (int ks = 0; ks < 4; ks++) {
            uint32_t a[4][4];
#pragma unroll
            for (int mt = 0; mt < 4; mt++) {
                // lanes: g0 rows 0-7 k-lo | g1 rows 8-15 k-lo | g2 rows 0-7 k-hi | g3 rows 8-15 k-hi
                uint32_t addr = aBase + (uint32_t)((mt * 16 + (g & 1) * 8 + r8) * PAD_BYTES
                                                  + ks * 32 + (g >> 1) * 16);
                ldsm_x4(a[mt][0], a[mt][1], a[mt][2], a[mt][3], addr);
            }
            uint32_t b[4][2];
#pragma unroll
            for (int pair = 0; pair < 2; pair++) {
                // matrices: [ntile 2p, k-lo] [ntile 2p, k-hi] [ntile 2p+1, k-lo] [ntile 2p+1, k-hi]
                int ntile = pair * 2 + (g >> 1);
                uint32_t addr = bBase + (uint32_t)((ntile * 8 + r8) * PAD_BYTES
                                                  + ks * 32 + (g & 1) * 16);
                ldsm_x4(b[pair * 2][0], b[pair * 2][1], b[pair * 2 + 1][0], b[pair * 2 + 1][1], addr);
            }
#pragma unroll
            for (int mt = 0; mt < 4; mt++)
#pragma unroll
                for (int nt = 0; nt < 4; nt++)
                    mma_bf16(c[mt][nt], a[mt][0], a[mt][1], a[mt][2], a[mt][3],
                             b[nt][0], b[nt][1]);
        }
        __syncthreads();
    }

    // ---------------- epilogue ----------------
    float dsa = fabsf(__ldg(ds));
    float rs[4][2];
#pragma unroll
    for (int mt = 0; mt < 4; mt++) { rs[mt][0] = 0.0f; rs[mt][1] = 0.0f; }

#pragma unroll
    for (int mt = 0; mt < 4; mt++) {
        int mrow = m0 + wm * 64 + mt * 16 + (l >> 2);
#pragma unroll
        for (int nt = 0; nt < 4; nt++) {
            int col = n0 + wn * 32 + nt * 8 + 2 * (l & 3);
            float i0 = dsa * sqrtf(fmaxf(1.0f - c[mt][nt][0], 0.0f));
            float i1 = dsa * sqrtf(fmaxf(1.0f - c[mt][nt][1], 0.0f));
            float i2 = dsa * sqrtf(fmaxf(1.0f - c[mt][nt][2], 0.0f));
            float i3 = dsa * sqrtf(fmaxf(1.0f - c[mt][nt][3], 0.0f));
            if (col < C_COLS) {             // col even, C_COLS even -> col+1 valid too
                rs[mt][0] += i0 + i1;
                rs[mt][1] += i2 + i3;
                *(float2*)(out + (size_t)mrow * C_COLS + col) = make_float2(i0, i1);
                *(float2*)(out + (size_t)(mrow + 8) * C_COLS + col) = make_float2(i2, i3);
            }
        }
    }
    // reduce row sums over the 4 lanes sharing a row (xor 1, 2), then atomics
#pragma unroll
    for (int mt = 0; mt < 4; mt++) {
#pragma unroll
        for (int h = 0; h < 2; h++) {
            float v = rs[mt][h];
            v += __shfl_xor_sync(0xffffffffu, v, 1);
            v += __shfl_xor_sync(0xffffffffu, v, 2);
            if ((l & 3) == 0) {
                int mrow = m0 + wm * 64 + mt * 16 + (l >> 2) + h * 8;
                atomicAdd(&g_rowsum[mrow], v);
            }
        }
    }
}

// ---------------------------------------------------------------------------
// Kernel 3: logits = -(iso + rowmean)/T, 2 float4 per thread (MLP=2).
// ---------------------------------------------------------------------------
#define F4_PER_ROW (C_COLS / 4)              // 250
#define FIN_TOTAL  (B_ROWS * F4_PER_ROW)     // 4,096,000
#define FIN_HALF   (FIN_TOTAL / 2)           // 2,048,000

__global__ void __launch_bounds__(256) finalize_kernel(float* __restrict__ out,
                                                       const float* __restrict__ temp) {
    unsigned v0 = blockIdx.x * 256u + threadIdx.x;
    if (v0 >= (unsigned)FIN_HALF) return;
    unsigned v1 = v0 + (unsigned)FIN_HALF;
    float invt = 1.0f / __ldg(temp);

    unsigned r0 = v0 / (unsigned)F4_PER_ROW;
    unsigned r1 = v1 / (unsigned)F4_PER_ROW;
    float4 x0 = *(float4*)(out + (size_t)v0 * 4);
    float4 x1 = *(float4*)(out + (size_t)v1 * 4);
    float m0 = __ldg(&g_rowsum[r0]) * (1.0f / (float)C_COLS);
    float m1 = __ldg(&g_rowsum[r1]) * (1.0f / (float)C_COLS);

    x0.x = -(x0.x + m0) * invt;  x0.y = -(x0.y + m0) * invt;
    x0.z = -(x0.z + m0) * invt;  x0.w = -(x0.w + m0) * invt;
    x1.x = -(x1.x + m1) * invt;  x1.y = -(x1.y + m1) * invt;
    x1.z = -(x1.z + m1) * invt;  x1.w = -(x1.w + m1) * invt;

    *(float4*)(out + (size_t)v0 * 4) = x0;
    *(float4*)(out + (size_t)v1 * 4) = x1;
}

// ---------------------------------------------------------------------------
extern "C" void kernel_launch(void* const* d_in, const int* in_sizes, int n_in,
                              void* d_out, int out_size) {
    const float* feat = (const float*)d_in[0];
    const float* prot = (const float*)d_in[1];
    const float* ds   = (const float*)d_in[2];
    const float* temp = (const float*)d_in[3];
    float* out = (float*)d_out;

    cudaFuncSetAttribute(gemm_kernel, cudaFuncAttributeMaxDynamicSharedMemorySize, GEMM_SMEM);

    norm_kernel<<<NORM_ROWS / 8, 256>>>(feat, prot);
    gemm_kernel<<<dim3(C_PAD / 128, B_ROWS / 128), 256, GEMM_SMEM>>>(ds, out);
    finalize_kernel<<<(FIN_HALF + 255) / 256, 256>>>(out, temp);
}